// round 4
// baseline (speedup 1.0000x reference)
#include <cuda_runtime.h>
#include <math.h>

#define D_   1024
#define H_   16
#define B_   4
#define N_   1024
#define S_   77
#define HD_  64
#define DF_  4096
#define EPS_ 1e-6f
#define SCALE_ 0.125f   // HD^-0.5

// ---------------- scratch (device globals; no allocation allowed) ----------
__device__ float g_mod [B_ * 6 * D_];                  // modulation (B,6D)
__device__ float g_tmp [B_ * N_ * D_];                 // ln/modulated activations
__device__ float g_qkv [B_ * N_ * 3 * D_];             // qkv, later reused for qc
__device__ float g_kvc [B_ * S_ * 2 * D_];             // cross kv
__device__ float g_attn[(size_t)B_ * H_ * N_ * N_];    // attn scores; reused as FF hidden
__device__ float g_sa  [B_ * N_ * D_];                 // attention outputs (pre-proj)

// ---------------- tf32 helpers ---------------------------------------------
__device__ __forceinline__ float f2tf32(float x) {
    unsigned r;
    asm("cvt.rna.tf32.f32 %0, %1;" : "=r"(r) : "f"(x));
    return __uint_as_float(r);
}

__device__ __forceinline__ void mma_tf32(float c[4], const unsigned a[4],
                                         unsigned b0, unsigned b1) {
    asm volatile(
        "mma.sync.aligned.m16n8k8.row.col.f32.tf32.tf32.f32 "
        "{%0,%1,%2,%3}, {%4,%5,%6,%7}, {%8,%9}, {%0,%1,%2,%3};\n"
        : "+f"(c[0]), "+f"(c[1]), "+f"(c[2]), "+f"(c[3])
        : "r"(a[0]), "r"(a[1]), "r"(a[2]), "r"(a[3]), "r"(b0), "r"(b1));
}

// ---------------- tensor-core tf32 GEMM ------------------------------------
// BM=128, BK=32, BN = 128 or 64. 2 x (BN/32) warps, each computes 64x32.
// MODE: 0 = bias only, 1 = bias+gelu, 2 = bias+residual, 3 = bias+gate*val+residual
template<bool TRANSB, int MODE, int BN>
__global__ __launch_bounds__(2 * BN) void mm_tc(
    const float* __restrict__ A,  int lda, long long aB, long long aH,
    const float* __restrict__ Bm, int ldb, long long bB, long long bH,
    float* __restrict__ C,        int ldc, long long cB, long long cH,
    const float* __restrict__ bias,
    const float* __restrict__ res,
    const float* __restrict__ gate,
    int M, int Ncols, int K, int Hdim)
{
    constexpr int WN       = BN / 32;        // warp columns
    constexpr int NTHREADS = 2 * BN;         // 2 warp rows x WN cols x 32
    constexpr int ANUM     = 512 / BN;       // float4 loads of A per thread
    constexpr int BNUM     = 4;              // float4 loads of B per thread
    constexpr int ASTR     = 36;             // A smem stride (m-major)
    constexpr int BSTR     = TRANSB ? 36 : (BN + 8);
    constexpr int BSMEM    = TRANSB ? (BN * 36) : (32 * (BN + 8));

    __shared__ float As[128 * ASTR];
    __shared__ float Bs[BSMEM];

    int z  = blockIdx.z;
    int zb = z / Hdim, zh = z - zb * Hdim;
    A  += (long long)zb * aB + (long long)zh * aH;
    Bm += (long long)zb * bB + (long long)zh * bH;
    C  += (long long)zb * cB + (long long)zh * cH;

    const int tid     = threadIdx.x;
    const int rowBase = blockIdx.y * 128;
    const int colBase = blockIdx.x * BN;

    const int warp  = tid >> 5;
    const int lane  = tid & 31;
    const int warpM = (warp / WN) * 64;
    const int warpN = (warp % WN) * 32;
    const int g     = lane >> 2;   // group id (0..7)
    const int tg    = lane & 3;    // thread in group

    float acc[4][4][4];
    #pragma unroll
    for (int i = 0; i < 4; i++)
        #pragma unroll
        for (int j = 0; j < 4; j++)
            #pragma unroll
            for (int t = 0; t < 4; t++) acc[i][j][t] = 0.f;

    float4 aR[ANUM], bR[BNUM];

    // ---- global load helpers (prefetch into registers) ----
    auto loadA = [&](int k0) {
        #pragma unroll
        for (int i = 0; i < ANUM; i++) {
            int idx = tid + i * NTHREADS;
            int m   = idx >> 3;
            int k4  = (idx & 7) * 4;
            int gr  = rowBase + m;
            if (gr < M)
                aR[i] = *(const float4*)(A + (long long)gr * lda + k0 + k4);
            else
                aR[i] = make_float4(0.f, 0.f, 0.f, 0.f);
        }
    };
    auto loadB = [&](int k0) {
        #pragma unroll
        for (int i = 0; i < BNUM; i++) {
            int idx = tid + i * NTHREADS;
            if (TRANSB) {
                int n  = idx >> 3;
                int k4 = (idx & 7) * 4;
                bR[i] = *(const float4*)(Bm + (long long)(colBase + n) * ldb + k0 + k4);
            } else {
                int kk = idx / (BN / 4);
                int n4 = (idx % (BN / 4)) * 4;
                bR[i] = *(const float4*)(Bm + (long long)(k0 + kk) * ldb + colBase + n4);
            }
        }
    };

    loadA(0);
    loadB(0);

    for (int k0 = 0; k0 < K; k0 += 32) {
        __syncthreads();
        // ---- store prefetched tiles to smem (with tf32 rounding) ----
        #pragma unroll
        for (int i = 0; i < ANUM; i++) {
            int idx = tid + i * NTHREADS;
            int m   = idx >> 3;
            int k4  = (idx & 7) * 4;
            float4 v = aR[i];
            v.x = f2tf32(v.x); v.y = f2tf32(v.y);
            v.z = f2tf32(v.z); v.w = f2tf32(v.w);
            *(float4*)&As[m * ASTR + k4] = v;
        }
        #pragma unroll
        for (int i = 0; i < BNUM; i++) {
            int idx = tid + i * NTHREADS;
            float4 v = bR[i];
            v.x = f2tf32(v.x); v.y = f2tf32(v.y);
            v.z = f2tf32(v.z); v.w = f2tf32(v.w);
            if (TRANSB) {
                int n  = idx >> 3;
                int k4 = (idx & 7) * 4;
                *(float4*)&Bs[n * BSTR + k4] = v;
            } else {
                int kk = idx / (BN / 4);
                int n4 = (idx % (BN / 4)) * 4;
                *(float4*)&Bs[kk * BSTR + n4] = v;
            }
        }
        __syncthreads();

        if (k0 + 32 < K) { loadA(k0 + 32); loadB(k0 + 32); }

        // ---- 4 mma k-slices over the 32-deep tile ----
        #pragma unroll
        for (int ks = 0; ks < 4; ks++) {
            int k = ks * 8 + tg;
            unsigned a[4][4];
            #pragma unroll
            for (int mt = 0; mt < 4; mt++) {
                int m = warpM + mt * 16 + g;
                a[mt][0] = __float_as_uint(As[m * ASTR + k]);
                a[mt][1] = __float_as_uint(As[(m + 8) * ASTR + k]);
                a[mt][2] = __float_as_uint(As[m * ASTR + k + 4]);
                a[mt][3] = __float_as_uint(As[(m + 8) * ASTR + k + 4]);
            }
            #pragma unroll
            for (int nt = 0; nt < 4; nt++) {
                int n = warpN + nt * 8 + g;
                unsigned b0, b1;
                if (TRANSB) {
                    b0 = __float_as_uint(Bs[n * BSTR + k]);
                    b1 = __float_as_uint(Bs[n * BSTR + k + 4]);
                } else {
                    b0 = __float_as_uint(Bs[(ks * 8 + tg) * BSTR + n]);
                    b1 = __float_as_uint(Bs[(ks * 8 + tg + 4) * BSTR + n]);
                }
                #pragma unroll
                for (int mt = 0; mt < 4; mt++)
                    mma_tf32(acc[mt][nt], a[mt], b0, b1);
            }
        }
    }

    // ---- epilogue ----
    #pragma unroll
    for (int mt = 0; mt < 4; mt++) {
        #pragma unroll
        for (int half = 0; half < 2; half++) {
            int row = rowBase + warpM + mt * 16 + g + half * 8;
            if (row >= M) continue;
            #pragma unroll
            for (int nt = 0; nt < 4; nt++) {
                int col = colBase + warpN + nt * 8 + tg * 2;
                #pragma unroll
                for (int e = 0; e < 2; e++) {
                    float v = acc[mt][nt][half * 2 + e];
                    int cc = col + e;
                    if (bias) v += bias[cc];
                    long long idx = (long long)row * ldc + cc;
                    if (MODE == 1) {
                        v = 0.5f * v * (1.0f + erff(v * 0.70710678118654752f));
                    } else if (MODE == 2) {
                        v = res[idx] + v;
                    } else if (MODE == 3) {
                        int bb = row >> 10;  // 1024 rows per batch
                        v = res[idx] + gate[(long long)bb * (6 * D_) + cc] * v;
                    }
                    C[idx] = v;
                }
            }
        }
    }
}

// ---------------- mod = silu(t_emb) @ ada_w + ada_b ------------------------
__global__ __launch_bounds__(256) void modk(const float* __restrict__ t_emb,
                                            const float* __restrict__ ada_w,
                                            const float* __restrict__ ada_b)
{
    __shared__ float sact[D_];
    int b   = blockIdx.y;
    int col = blockIdx.x * 256 + threadIdx.x;
    for (int i = threadIdx.x; i < D_; i += 256) {
        float t = t_emb[b * D_ + i];
        sact[i] = t / (1.f + expf(-t));
    }
    __syncthreads();
    float acc = ada_b[col];
    for (int k = 0; k < D_; k++)
        acc += sact[k] * ada_w[(long long)k * (6 * D_) + col];
    g_mod[(long long)b * 6 * D_ + col] = acc;
}

// ---------------- layernorm (+ optional adaLN modulation) ------------------
__global__ __launch_bounds__(256) void ln_mod(const float* __restrict__ x,
                                              float* __restrict__ out,
                                              const float* __restrict__ mod,
                                              int scaleOff, int shiftOff)
{
    long long row = blockIdx.x;
    int b = (int)(row >> 10);
    const float4* p = (const float4*)(x + row * D_);
    float4* q = (float4*)(out + row * D_);
    int tid = threadIdx.x;
    float4 v = p[tid];
    float s  = v.x + v.y + v.z + v.w;
    float s2 = v.x*v.x + v.y*v.y + v.z*v.z + v.w*v.w;
    __shared__ float r1[8], r2[8];
    __shared__ float s_mean, s_rstd;
    #pragma unroll
    for (int o = 16; o > 0; o >>= 1) {
        s  += __shfl_xor_sync(0xffffffffu, s,  o);
        s2 += __shfl_xor_sync(0xffffffffu, s2, o);
    }
    if ((tid & 31) == 0) { r1[tid >> 5] = s; r2[tid >> 5] = s2; }
    __syncthreads();
    if (tid == 0) {
        float a = 0.f, bb = 0.f;
        for (int i = 0; i < 8; i++) { a += r1[i]; bb += r2[i]; }
        float mean = a * (1.f / D_);
        float var  = bb * (1.f / D_) - mean * mean;
        s_mean = mean;
        s_rstd = rsqrtf(var + EPS_);
    }
    __syncthreads();
    float mean = s_mean, rstd = s_rstd;
    float4 o;
    o.x = (v.x - mean) * rstd;
    o.y = (v.y - mean) * rstd;
    o.z = (v.z - mean) * rstd;
    o.w = (v.w - mean) * rstd;
    if (mod) {
        const float* mrow = mod + (long long)b * 6 * D_;
        int col = tid * 4;
        o.x = o.x * (1.f + mrow[scaleOff + col + 0]) + mrow[shiftOff + col + 0];
        o.y = o.y * (1.f + mrow[scaleOff + col + 1]) + mrow[shiftOff + col + 1];
        o.z = o.z * (1.f + mrow[scaleOff + col + 2]) + mrow[shiftOff + col + 2];
        o.w = o.w * (1.f + mrow[scaleOff + col + 3]) + mrow[shiftOff + col + 3];
    }
    q[tid] = o;
}

// ---------------- softmax over rows of 1024 (applies SCALE) ----------------
__global__ __launch_bounds__(256) void softmax1024(float* __restrict__ attn)
{
    long long row = blockIdx.x;
    float4* p = (float4*)(attn + row * 1024);
    int tid = threadIdx.x;
    float4 v = p[tid];
    v.x *= SCALE_; v.y *= SCALE_; v.z *= SCALE_; v.w *= SCALE_;
    float m = fmaxf(fmaxf(v.x, v.y), fmaxf(v.z, v.w));
    __shared__ float red[8];
    __shared__ float bval;
    #pragma unroll
    for (int o = 16; o > 0; o >>= 1) m = fmaxf(m, __shfl_xor_sync(0xffffffffu, m, o));
    if ((tid & 31) == 0) red[tid >> 5] = m;
    __syncthreads();
    if (tid == 0) {
        float t = red[0];
        for (int i = 1; i < 8; i++) t = fmaxf(t, red[i]);
        bval = t;
    }
    __syncthreads();
    m = bval;
    v.x = expf(v.x - m); v.y = expf(v.y - m);
    v.z = expf(v.z - m); v.w = expf(v.w - m);
    float s = v.x + v.y + v.z + v.w;
    #pragma unroll
    for (int o = 16; o > 0; o >>= 1) s += __shfl_xor_sync(0xffffffffu, s, o);
    __syncthreads();
    if ((tid & 31) == 0) red[tid >> 5] = s;
    __syncthreads();
    if (tid == 0) {
        float t = 0.f;
        for (int i = 0; i < 8; i++) t += red[i];
        bval = 1.f / t;
    }
    __syncthreads();
    float inv = bval;
    v.x *= inv; v.y *= inv; v.z *= inv; v.w *= inv;
    p[tid] = v;
}

// ---------------- fused cross-attention (S=77) -----------------------------
__global__ __launch_bounds__(128) void cross_attn(const unsigned char* __restrict__ mask)
{
    int n = blockIdx.x, h = blockIdx.y, b = blockIdx.z;
    __shared__ float qv[HD_];
    __shared__ float sc[S_];
    __shared__ float s_m, s_sum;
    int tid = threadIdx.x;
    if (tid < HD_)
        qv[tid] = g_qkv[(long long)(b * N_ + n) * D_ + h * HD_ + tid];  // qc lives in g_qkv
    __syncthreads();
    if (tid < S_) {
        const float* kp = g_kvc + ((long long)(b * S_ + tid) * 2) * D_ + h * HD_;
        float s = 0.f;
        #pragma unroll
        for (int d = 0; d < HD_; d++) s += qv[d] * kp[d];
        s *= SCALE_;
        if (mask[b * S_ + tid]) s = -1e30f;
        sc[tid] = s;
    }
    __syncthreads();
    if (tid == 0) {
        float m = -1e30f;
        for (int i = 0; i < S_; i++) m = fmaxf(m, sc[i]);
        s_m = m;
    }
    __syncthreads();
    if (tid < S_) sc[tid] = expf(sc[tid] - s_m);
    __syncthreads();
    if (tid == 0) {
        float s = 0.f;
        for (int i = 0; i < S_; i++) s += sc[i];
        s_sum = s;
    }
    __syncthreads();
    if (tid < HD_) {
        float o = 0.f;
        for (int si = 0; si < S_; si++)
            o += sc[si] * g_kvc[((long long)(b * S_ + si) * 2 + 1) * D_ + h * HD_ + tid];
        g_sa[(long long)(b * N_ + n) * D_ + h * HD_ + tid] = o / s_sum;
    }
}

// ---------------- host orchestration ---------------------------------------
extern "C" void kernel_launch(void* const* d_in, const int* in_sizes, int n_in,
                              void* d_out, int out_size)
{
    const float* x       = (const float*)d_in[0];
    const float* t_emb   = (const float*)d_in[1];
    const float* context = (const float*)d_in[2];
    const unsigned char* cmask = (const unsigned char*)d_in[3];
    const float* ada_w = (const float*)d_in[4];  const float* ada_b = (const float*)d_in[5];
    const float* qkv_w = (const float*)d_in[6];  const float* qkv_b = (const float*)d_in[7];
    const float* sa_w  = (const float*)d_in[8];  const float* sa_b  = (const float*)d_in[9];
    const float* q_w   = (const float*)d_in[10]; const float* q_b   = (const float*)d_in[11];
    const float* kv_w  = (const float*)d_in[12]; const float* kv_b  = (const float*)d_in[13];
    const float* ca_w  = (const float*)d_in[14]; const float* ca_b  = (const float*)d_in[15];
    const float* fc1_w = (const float*)d_in[16]; const float* fc1_b = (const float*)d_in[17];
    const float* fc2_w = (const float*)d_in[18]; const float* fc2_b = (const float*)d_in[19];
    float* out = (float*)d_out;

    float *p_mod, *p_tmp, *p_qkv, *p_kvc, *p_attn, *p_sa;
    cudaGetSymbolAddress((void**)&p_mod,  g_mod);
    cudaGetSymbolAddress((void**)&p_tmp,  g_tmp);
    cudaGetSymbolAddress((void**)&p_qkv,  g_qkv);
    cudaGetSymbolAddress((void**)&p_kvc,  g_kvc);
    cudaGetSymbolAddress((void**)&p_attn, g_attn);
    cudaGetSymbolAddress((void**)&p_sa,   g_sa);

    // 1. modulation vector
    modk<<<dim3(6 * D_ / 256, B_), 256>>>(t_emb, ada_w, ada_b);
    // 2. xm1 = ln(x)*(1+scale_sa)+shift_sa
    ln_mod<<<B_ * N_, 256>>>(x, p_tmp, p_mod, D_, 0);
    // 3. qkv
    mm_tc<false, 0, 128><<<dim3(3 * D_ / 128, B_ * N_ / 128, 1), 256>>>(
        p_tmp, D_, 0, 0, qkv_w, 3 * D_, 0, 0, p_qkv, 3 * D_, 0, 0,
        qkv_b, nullptr, nullptr, B_ * N_, 3 * D_, D_, 1);
    // 4. scores = Q @ K^T  (batched over 64 (b,h))
    mm_tc<true, 0, 128><<<dim3(N_ / 128, N_ / 128, B_ * H_), 256>>>(
        p_qkv, 3 * D_, (long long)N_ * 3 * D_, HD_,
        p_qkv + D_, 3 * D_, (long long)N_ * 3 * D_, HD_,
        p_attn, N_, (long long)H_ * N_ * N_, (long long)N_ * N_,
        nullptr, nullptr, nullptr, N_, N_, HD_, H_);
    // 5. softmax
    softmax1024<<<B_ * H_ * N_, 256>>>(p_attn);
    // 6. P @ V   (BN=64, batched over (b,h))
    mm_tc<false, 0, 64><<<dim3(1, N_ / 128, B_ * H_), 128>>>(
        p_attn, N_, (long long)H_ * N_ * N_, (long long)N_ * N_,
        p_qkv + 2 * D_, 3 * D_, (long long)N_ * 3 * D_, HD_,
        p_sa, D_, (long long)N_ * D_, HD_,
        nullptr, nullptr, nullptr, N_, HD_, N_, H_);
    // 7. x = x + gate_sa * (sa @ W + b)
    mm_tc<false, 3, 128><<<dim3(D_ / 128, B_ * N_ / 128, 1), 256>>>(
        p_sa, D_, 0, 0, sa_w, D_, 0, 0, out, D_, 0, 0,
        sa_b, x, p_mod + 2 * D_, B_ * N_, D_, D_, 1);
    // 8. xn2 = ln(x)
    ln_mod<<<B_ * N_, 256>>>(out, p_tmp, nullptr, 0, 0);
    // 9. qc (reuse g_qkv)
    mm_tc<false, 0, 128><<<dim3(D_ / 128, B_ * N_ / 128, 1), 256>>>(
        p_tmp, D_, 0, 0, q_w, D_, 0, 0, p_qkv, D_, 0, 0,
        q_b, nullptr, nullptr, B_ * N_, D_, D_, 1);
    // 10. kv from context (M=308, guarded)
    mm_tc<false, 0, 128><<<dim3(2 * D_ / 128, (B_ * S_ + 127) / 128, 1), 256>>>(
        context, D_, 0, 0, kv_w, 2 * D_, 0, 0, p_kvc, 2 * D_, 0, 0,
        kv_b, nullptr, nullptr, B_ * S_, 2 * D_, D_, 1);
    // 11. fused cross-attention -> g_sa
    cross_attn<<<dim3(N_, H_, B_), 128>>>(cmask);
    // 12. x = x + (ca @ W + b)
    mm_tc<false, 2, 128><<<dim3(D_ / 128, B_ * N_ / 128, 1), 256>>>(
        p_sa, D_, 0, 0, ca_w, D_, 0, 0, out, D_, 0, 0,
        ca_b, out, nullptr, B_ * N_, D_, D_, 1);
    // 13. xm3 = ln(x)*(1+scale_ff)+shift_ff
    ln_mod<<<B_ * N_, 256>>>(out, p_tmp, p_mod, 4 * D_, 3 * D_);
    // 14. h = gelu(xm3 @ fc1 + b)   (hidden reuses g_attn)
    mm_tc<false, 1, 128><<<dim3(DF_ / 128, B_ * N_ / 128, 1), 256>>>(
        p_tmp, D_, 0, 0, fc1_w, DF_, 0, 0, p_attn, DF_, 0, 0,
        fc1_b, nullptr, nullptr, B_ * N_, DF_, D_, 1);
    // 15. x = x + gate_ff * (h @ fc2 + b)
    mm_tc<false, 3, 128><<<dim3(D_ / 128, B_ * N_ / 128, 1), 256>>>(
        p_attn, DF_, 0, 0, fc2_w, D_, 0, 0, out, D_, 0, 0,
        fc2_b, out, p_mod + 5 * D_, B_ * N_, D_, DF_, 1);
}

// round 6
// speedup vs baseline: 1.0380x; 1.0380x over previous
#include <cuda_runtime.h>
#include <math.h>

#define D_   1024
#define H_   16
#define B_   4
#define N_   1024
#define S_   77
#define HD_  64
#define DF_  4096
#define EPS_ 1e-6f
#define SCALE_ 0.125f   // HD^-0.5

// ---------------- scratch (device globals; no allocation allowed) ----------
__device__ float g_mod [B_ * 6 * D_];                  // modulation (B,6D)
__device__ float g_tmp [B_ * N_ * D_];                 // ln/modulated activations
__device__ float g_qkv [B_ * N_ * 3 * D_];             // qkv, later reused for qc
__device__ float g_kvc [B_ * S_ * 2 * D_];             // cross kv
__device__ float g_attn[(size_t)B_ * N_ * DF_];        // FF hidden
__device__ float g_sa  [B_ * N_ * D_];                 // attention outputs (pre-proj)

// ---------------- tf32 helpers ---------------------------------------------
__device__ __forceinline__ float f2tf32(float x) {
    unsigned r;
    asm("cvt.rna.tf32.f32 %0, %1;" : "=r"(r) : "f"(x));
    return __uint_as_float(r);
}

__device__ __forceinline__ void mma_tf32(float c[4], const unsigned a[4],
                                         unsigned b0, unsigned b1) {
    asm volatile(
        "mma.sync.aligned.m16n8k8.row.col.f32.tf32.tf32.f32 "
        "{%0,%1,%2,%3}, {%4,%5,%6,%7}, {%8,%9}, {%0,%1,%2,%3};\n"
        : "+f"(c[0]), "+f"(c[1]), "+f"(c[2]), "+f"(c[3])
        : "r"(a[0]), "r"(a[1]), "r"(a[2]), "r"(a[3]), "r"(b0), "r"(b1));
}

__device__ __forceinline__ void cp_async16(void* smem_dst, const void* gmem_src) {
    unsigned dst = (unsigned)__cvta_generic_to_shared(smem_dst);
    asm volatile("cp.async.cg.shared.global [%0], [%1], 16;\n"
                 :: "r"(dst), "l"(gmem_src));
}
__device__ __forceinline__ void cp_commit() {
    asm volatile("cp.async.commit_group;\n" ::: "memory");
}
template<int N>
__device__ __forceinline__ void cp_wait() {
    asm volatile("cp.async.wait_group %0;\n" :: "n"(N) : "memory");
}

// ---------------- fused flash self-attention (tf32) -------------------------
// grid (N/128, B*H), 256 threads = 8 warps; each warp owns 16 Q rows.
// KV streamed in 128-row tiles, double-buffered via cp.async.
// smem layout (floats): Qs[9216] Ks0[9216] Ks1[9216] Vs0[9216] Vs1[9216]
#define FA_TILE  9216          // 128 * 72 floats
#define FA_SMEM  (5 * FA_TILE * 4)

__global__ __launch_bounds__(256) void flash_attn()
{
    extern __shared__ float sm[];
    float* Qs = sm;
    float* Ks[2] = { sm + FA_TILE,     sm + 2 * FA_TILE };
    float* Vs[2] = { sm + 3 * FA_TILE, sm + 4 * FA_TILE };

    const int tid = threadIdx.x;
    const int w    = tid >> 5;
    const int lane = tid & 31;
    const int g    = lane >> 2;
    const int tg   = lane & 3;

    const int bh = blockIdx.y;
    const int b  = bh >> 4, h = bh & 15;
    const int qrow0 = blockIdx.x * 128;

    const float* Qp = g_qkv + (long long)b * N_ * 3 * D_ + h * HD_;
    const float* Kp = Qp + D_;
    const float* Vp = Qp + 2 * D_;

    // ---- load Q block (scaled + tf32-rounded) ----
    #pragma unroll
    for (int i = 0; i < 8; i++) {
        int c   = tid + i * 256;          // 0..2047
        int row = c >> 4;
        int col = (c & 15) * 4;
        float4 v = *(const float4*)(Qp + (long long)(qrow0 + row) * 3072 + col);
        v.x = f2tf32(v.x * SCALE_); v.y = f2tf32(v.y * SCALE_);
        v.z = f2tf32(v.z * SCALE_); v.w = f2tf32(v.w * SCALE_);
        *(float4*)&Qs[row * 72 + col] = v;
    }

    // ---- prologue: async-load KV tile 0 into stage 0 ----
    auto loadTile = [&](const float* gbase, float* sbase) {
        #pragma unroll
        for (int i = 0; i < 8; i++) {
            int c   = tid + i * 256;
            int row = c >> 4;
            int col = (c & 15) * 4;
            cp_async16(sbase + row * 72 + col,
                       gbase + (long long)row * 3072 + col);
        }
    };
    loadTile(Kp, Ks[0]);
    loadTile(Vp, Vs[0]);
    cp_commit();

    __syncthreads();

    // ---- Q fragments (per warp: 16 rows, K=64 -> 8 k-slices) ----
    unsigned qa[8][4];
    {
        int r0 = w * 16 + g;
        #pragma unroll
        for (int ks = 0; ks < 8; ks++) {
            qa[ks][0] = __float_as_uint(Qs[r0 * 72 + ks * 8 + tg]);
            qa[ks][1] = __float_as_uint(Qs[(r0 + 8) * 72 + ks * 8 + tg]);
            qa[ks][2] = __float_as_uint(Qs[r0 * 72 + ks * 8 + tg + 4]);
            qa[ks][3] = __float_as_uint(Qs[(r0 + 8) * 72 + ks * 8 + tg + 4]);
        }
    }

    float o[8][4];
    #pragma unroll
    for (int i = 0; i < 8; i++)
        #pragma unroll
        for (int j = 0; j < 4; j++) o[i][j] = 0.f;
    float m0 = -1e30f, m1 = -1e30f, l0 = 0.f, l1 = 0.f;

    const unsigned fullm = 0xffffffffu;
    const int srcA = (lane & ~3) | (tg >> 1);
    const int srcB = srcA + 2;

    for (int t = 0; t < 8; t++) {
        if (t + 1 < 8) {
            loadTile(Kp + (long long)(t + 1) * 128 * 3072, Ks[(t + 1) & 1]);
            loadTile(Vp + (long long)(t + 1) * 128 * 3072, Vs[(t + 1) & 1]);
            cp_commit();
            cp_wait<1>();
        } else {
            cp_wait<0>();
        }
        __syncthreads();

        const float* K_ = Ks[t & 1];
        const float* V_ = Vs[t & 1];

        // ---- S = Qblk @ Ktile^T  (16 x 128 per warp) ----
        float s[16][4];
        #pragma unroll
        for (int nt = 0; nt < 16; nt++) {
            s[nt][0] = s[nt][1] = s[nt][2] = s[nt][3] = 0.f;
            #pragma unroll
            for (int ks = 0; ks < 8; ks++) {
                unsigned b0 = __float_as_uint(K_[(nt * 8 + g) * 72 + ks * 8 + tg]);
                unsigned b1 = __float_as_uint(K_[(nt * 8 + g) * 72 + ks * 8 + tg + 4]);
                mma_tf32(s[nt], qa[ks], b0, b1);
            }
        }

        // ---- online softmax ----
        float mx0 = -1e30f, mx1 = -1e30f;
        #pragma unroll
        for (int nt = 0; nt < 16; nt++) {
            mx0 = fmaxf(mx0, fmaxf(s[nt][0], s[nt][1]));
            mx1 = fmaxf(mx1, fmaxf(s[nt][2], s[nt][3]));
        }
        mx0 = fmaxf(mx0, __shfl_xor_sync(fullm, mx0, 1));
        mx0 = fmaxf(mx0, __shfl_xor_sync(fullm, mx0, 2));
        mx1 = fmaxf(mx1, __shfl_xor_sync(fullm, mx1, 1));
        mx1 = fmaxf(mx1, __shfl_xor_sync(fullm, mx1, 2));
        float mn0 = fmaxf(m0, mx0), mn1 = fmaxf(m1, mx1);
        float sc0 = __expf(m0 - mn0), sc1 = __expf(m1 - mn1);
        float rs0 = 0.f, rs1 = 0.f;
        #pragma unroll
        for (int nt = 0; nt < 16; nt++) {
            s[nt][0] = __expf(s[nt][0] - mn0);
            s[nt][1] = __expf(s[nt][1] - mn0);
            s[nt][2] = __expf(s[nt][2] - mn1);
            s[nt][3] = __expf(s[nt][3] - mn1);
            rs0 += s[nt][0] + s[nt][1];
            rs1 += s[nt][2] + s[nt][3];
        }
        rs0 += __shfl_xor_sync(fullm, rs0, 1);
        rs0 += __shfl_xor_sync(fullm, rs0, 2);
        rs1 += __shfl_xor_sync(fullm, rs1, 1);
        rs1 += __shfl_xor_sync(fullm, rs1, 2);
        l0 = l0 * sc0 + rs0;
        l1 = l1 * sc1 + rs1;
        m0 = mn0; m1 = mn1;
        #pragma unroll
        for (int nt = 0; nt < 8; nt++) {
            o[nt][0] *= sc0; o[nt][1] *= sc0;
            o[nt][2] *= sc1; o[nt][3] *= sc1;
        }

        // ---- O += P @ Vtile : remap P (C-layout) to A-fragments via shuffles --
        #pragma unroll
        for (int kt = 0; kt < 16; kt++) {
            float p0 = s[kt][0], p1 = s[kt][1], p2 = s[kt][2], p3 = s[kt][3];
            float x0 = __shfl_sync(fullm, p0, srcA);
            float x1 = __shfl_sync(fullm, p1, srcA);
            float y0 = __shfl_sync(fullm, p2, srcA);
            float y1 = __shfl_sync(fullm, p3, srcA);
            float x0b = __shfl_sync(fullm, p0, srcB);
            float x1b = __shfl_sync(fullm, p1, srcB);
            float y0b = __shfl_sync(fullm, p2, srcB);
            float y1b = __shfl_sync(fullm, p3, srcB);
            unsigned a[4];
            a[0] = __float_as_uint((tg & 1) ? x1  : x0);
            a[1] = __float_as_uint((tg & 1) ? y1  : y0);
            a[2] = __float_as_uint((tg & 1) ? x1b : x0b);
            a[3] = __float_as_uint((tg & 1) ? y1b : y0b);
            #pragma unroll
            for (int nt = 0; nt < 8; nt++) {
                unsigned b0 = __float_as_uint(V_[(kt * 8 + tg) * 72 + nt * 8 + g]);
                unsigned b1 = __float_as_uint(V_[(kt * 8 + tg + 4) * 72 + nt * 8 + g]);
                mma_tf32(o[nt], a, b0, b1);
            }
        }
        __syncthreads();
    }

    // ---- normalize and write ----
    float inv0 = 1.f / l0, inv1 = 1.f / l1;
    int row0 = qrow0 + w * 16 + g;
    float* op = g_sa + (long long)(b * N_ + row0) * D_ + h * HD_;
    #pragma unroll
    for (int nt = 0; nt < 8; nt++) {
        int col = nt * 8 + tg * 2;
        float2 lo = make_float2(o[nt][0] * inv0, o[nt][1] * inv0);
        float2 hi = make_float2(o[nt][2] * inv1, o[nt][3] * inv1);
        *(float2*)(op + col)            = lo;
        *(float2*)(op + 8 * D_ + col)   = hi;
    }
}

// ---------------- tensor-core tf32 GEMM ------------------------------------
// BM=128, BK=32, BN=128. 8 warps, each computes 64x32.
// MODE: 0 = bias only, 1 = bias+gelu, 2 = bias+residual, 3 = bias+gate*val+residual
template<int MODE>
__global__ __launch_bounds__(256) void mm_tc(
    const float* __restrict__ A,  int lda,
    const float* __restrict__ Bm, int ldb,
    float* __restrict__ C,        int ldc,
    const float* __restrict__ bias,
    const float* __restrict__ res,
    const float* __restrict__ gate,
    int M, int Ncols, int K)
{
    constexpr int BN       = 128;
    constexpr int NTHREADS = 256;
    constexpr int ANUM     = 4;
    constexpr int BNUM     = 4;
    constexpr int ASTR     = 36;
    constexpr int BSTR     = BN + 8;

    __shared__ float As[128 * ASTR];
    __shared__ float Bs[32 * BSTR];

    const int tid     = threadIdx.x;
    const int rowBase = blockIdx.y * 128;
    const int colBase = blockIdx.x * BN;

    const int warp  = tid >> 5;
    const int lane  = tid & 31;
    const int warpM = (warp / 4) * 64;
    const int warpN = (warp % 4) * 32;
    const int g     = lane >> 2;
    const int tg    = lane & 3;

    float acc[4][4][4];
    #pragma unroll
    for (int i = 0; i < 4; i++)
        #pragma unroll
        for (int j = 0; j < 4; j++)
            #pragma unroll
            for (int t = 0; t < 4; t++) acc[i][j][t] = 0.f;

    float4 aR[ANUM], bR[BNUM];

    auto loadA = [&](int k0) {
        #pragma unroll
        for (int i = 0; i < ANUM; i++) {
            int idx = tid + i * NTHREADS;
            int m   = idx >> 3;
            int k4  = (idx & 7) * 4;
            int gr  = rowBase + m;
            if (gr < M)
                aR[i] = *(const float4*)(A + (long long)gr * lda + k0 + k4);
            else
                aR[i] = make_float4(0.f, 0.f, 0.f, 0.f);
        }
    };
    auto loadB = [&](int k0) {
        #pragma unroll
        for (int i = 0; i < BNUM; i++) {
            int idx = tid + i * NTHREADS;
            int kk  = idx >> 5;
            int n4  = (idx & 31) * 4;
            bR[i] = *(const float4*)(Bm + (long long)(k0 + kk) * ldb + colBase + n4);
        }
    };

    loadA(0);
    loadB(0);

    for (int k0 = 0; k0 < K; k0 += 32) {
        __syncthreads();
        #pragma unroll
        for (int i = 0; i < ANUM; i++) {
            int idx = tid + i * NTHREADS;
            int m   = idx >> 3;
            int k4  = (idx & 7) * 4;
            float4 v = aR[i];
            v.x = f2tf32(v.x); v.y = f2tf32(v.y);
            v.z = f2tf32(v.z); v.w = f2tf32(v.w);
            *(float4*)&As[m * ASTR + k4] = v;
        }
        #pragma unroll
        for (int i = 0; i < BNUM; i++) {
            int idx = tid + i * NTHREADS;
            int kk  = idx >> 5;
            int n4  = (idx & 31) * 4;
            float4 v = bR[i];
            v.x = f2tf32(v.x); v.y = f2tf32(v.y);
            v.z = f2tf32(v.z); v.w = f2tf32(v.w);
            *(float4*)&Bs[kk * BSTR + n4] = v;
        }
        __syncthreads();

        if (k0 + 32 < K) { loadA(k0 + 32); loadB(k0 + 32); }

        #pragma unroll
        for (int ks = 0; ks < 4; ks++) {
            int k = ks * 8 + tg;
            unsigned a[4][4];
            #pragma unroll
            for (int mt = 0; mt < 4; mt++) {
                int m = warpM + mt * 16 + g;
                a[mt][0] = __float_as_uint(As[m * ASTR + k]);
                a[mt][1] = __float_as_uint(As[(m + 8) * ASTR + k]);
                a[mt][2] = __float_as_uint(As[m * ASTR + k + 4]);
                a[mt][3] = __float_as_uint(As[(m + 8) * ASTR + k + 4]);
            }
            #pragma unroll
            for (int nt = 0; nt < 4; nt++) {
                int n = warpN + nt * 8 + g;
                unsigned b0 = __float_as_uint(Bs[k * BSTR + n]);
                unsigned b1 = __float_as_uint(Bs[(k + 4) * BSTR + n]);
                #pragma unroll
                for (int mt = 0; mt < 4; mt++)
                    mma_tf32(acc[mt][nt], a[mt], b0, b1);
            }
        }
    }

    #pragma unroll
    for (int mt = 0; mt < 4; mt++) {
        #pragma unroll
        for (int half = 0; half < 2; half++) {
            int row = rowBase + warpM + mt * 16 + g + half * 8;
            if (row >= M) continue;
            #pragma unroll
            for (int nt = 0; nt < 4; nt++) {
                int col = colBase + warpN + nt * 8 + tg * 2;
                #pragma unroll
                for (int e = 0; e < 2; e++) {
                    float v = acc[mt][nt][half * 2 + e];
                    int cc = col + e;
                    if (bias) v += bias[cc];
                    long long idx = (long long)row * ldc + cc;
                    if (MODE == 1) {
                        v = 0.5f * v * (1.0f + erff(v * 0.70710678118654752f));
                    } else if (MODE == 2) {
                        v = res[idx] + v;
                    } else if (MODE == 3) {
                        int bb = row >> 10;
                        v = res[idx] + gate[(long long)bb * (6 * D_) + cc] * v;
                    }
                    C[idx] = v;
                }
            }
        }
    }
}

// ---------------- mod = silu(t_emb) @ ada_w + ada_b ------------------------
__global__ __launch_bounds__(256) void modk(const float* __restrict__ t_emb,
                                            const float* __restrict__ ada_w,
                                            const float* __restrict__ ada_b)
{
    __shared__ float sact[D_];
    int b   = blockIdx.y;
    int col = blockIdx.x * 256 + threadIdx.x;
    for (int i = threadIdx.x; i < D_; i += 256) {
        float t = t_emb[b * D_ + i];
        sact[i] = t / (1.f + expf(-t));
    }
    __syncthreads();
    float acc = ada_b[col];
    for (int k = 0; k < D_; k++)
        acc += sact[k] * ada_w[(long long)k * (6 * D_) + col];
    g_mod[(long long)b * 6 * D_ + col] = acc;
}

// ---------------- layernorm (+ optional adaLN modulation) ------------------
__global__ __launch_bounds__(256) void ln_mod(const float* __restrict__ x,
                                              float* __restrict__ out,
                                              const float* __restrict__ mod,
                                              int scaleOff, int shiftOff)
{
    long long row = blockIdx.x;
    int b = (int)(row >> 10);
    const float4* p = (const float4*)(x + row * D_);
    float4* q = (float4*)(out + row * D_);
    int tid = threadIdx.x;
    float4 v = p[tid];
    float s  = v.x + v.y + v.z + v.w;
    float s2 = v.x*v.x + v.y*v.y + v.z*v.z + v.w*v.w;
    __shared__ float r1[8], r2[8];
    __shared__ float s_mean, s_rstd;
    #pragma unroll
    for (int o = 16; o > 0; o >>= 1) {
        s  += __shfl_xor_sync(0xffffffffu, s,  o);
        s2 += __shfl_xor_sync(0xffffffffu, s2, o);
    }
    if ((tid & 31) == 0) { r1[tid >> 5] = s; r2[tid >> 5] = s2; }
    __syncthreads();
    if (tid == 0) {
        float a = 0.f, bb = 0.f;
        for (int i = 0; i < 8; i++) { a += r1[i]; bb += r2[i]; }
        float mean = a * (1.f / D_);
        float var  = bb * (1.f / D_) - mean * mean;
        s_mean = mean;
        s_rstd = rsqrtf(var + EPS_);
    }
    __syncthreads();
    float mean = s_mean, rstd = s_rstd;
    float4 o;
    o.x = (v.x - mean) * rstd;
    o.y = (v.y - mean) * rstd;
    o.z = (v.z - mean) * rstd;
    o.w = (v.w - mean) * rstd;
    if (mod) {
        const float* mrow = mod + (long long)b * 6 * D_;
        int col = tid * 4;
        o.x = o.x * (1.f + mrow[scaleOff + col + 0]) + mrow[shiftOff + col + 0];
        o.y = o.y * (1.f + mrow[scaleOff + col + 1]) + mrow[shiftOff + col + 1];
        o.z = o.z * (1.f + mrow[scaleOff + col + 2]) + mrow[shiftOff + col + 2];
        o.w = o.w * (1.f + mrow[scaleOff + col + 3]) + mrow[shiftOff + col + 3];
    }
    q[tid] = o;
}

// ---------------- fused cross-attention (S=77) -----------------------------
__global__ __launch_bounds__(128) void cross_attn(const unsigned char* __restrict__ mask)
{
    int n = blockIdx.x, h = blockIdx.y, b = blockIdx.z;
    __shared__ float qv[HD_];
    __shared__ float sc[S_];
    __shared__ float s_m, s_sum;
    int tid = threadIdx.x;
    if (tid < HD_)
        qv[tid] = g_qkv[(long long)(b * N_ + n) * D_ + h * HD_ + tid];  // qc lives in g_qkv
    __syncthreads();
    if (tid < S_) {
        const float* kp = g_kvc + ((long long)(b * S_ + tid) * 2) * D_ + h * HD_;
        float s = 0.f;
        #pragma unroll
        for (int d = 0; d < HD_; d++) s += qv[d] * kp[d];
        s *= SCALE_;
        if (mask[b * S_ + tid]) s = -1e30f;
        sc[tid] = s;
    }
    __syncthreads();
    if (tid == 0) {
        float m = -1e30f;
        for (int i = 0; i < S_; i++) m = fmaxf(m, sc[i]);
        s_m = m;
    }
    __syncthreads();
    if (tid < S_) sc[tid] = expf(sc[tid] - s_m);
    __syncthreads();
    if (tid == 0) {
        float s = 0.f;
        for (int i = 0; i < S_; i++) s += sc[i];
        s_sum = s;
    }
    __syncthreads();
    if (tid < HD_) {
        float o = 0.f;
        for (int si = 0; si < S_; si++)
            o += sc[si] * g_kvc[((long long)(b * S_ + si) * 2 + 1) * D_ + h * HD_ + tid];
        g_sa[(long long)(b * N_ + n) * D_ + h * HD_ + tid] = o / s_sum;
    }
}

// ---------------- host orchestration ---------------------------------------
extern "C" void kernel_launch(void* const* d_in, const int* in_sizes, int n_in,
                              void* d_out, int out_size)
{
    const float* x       = (const float*)d_in[0];
    const float* t_emb   = (const float*)d_in[1];
    const float* context = (const float*)d_in[2];
    const unsigned char* cmask = (const unsigned char*)d_in[3];
    const float* ada_w = (const float*)d_in[4];  const float* ada_b = (const float*)d_in[5];
    const float* qkv_w = (const float*)d_in[6];  const float* qkv_b = (const float*)d_in[7];
    const float* sa_w  = (const float*)d_in[8];  const float* sa_b  = (const float*)d_in[9];
    const float* q_w   = (const float*)d_in[10]; const float* q_b   = (const float*)d_in[11];
    const float* kv_w  = (const float*)d_in[12]; const float* kv_b  = (const float*)d_in[13];
    const float* ca_w  = (const float*)d_in[14]; const float* ca_b  = (const float*)d_in[15];
    const float* fc1_w = (const float*)d_in[16]; const float* fc1_b = (const float*)d_in[17];
    const float* fc2_w = (const float*)d_in[18]; const float* fc2_b = (const float*)d_in[19];
    float* out = (float*)d_out;

    float *p_mod, *p_tmp, *p_qkv, *p_kvc, *p_attn, *p_sa;
    cudaGetSymbolAddress((void**)&p_mod,  g_mod);
    cudaGetSymbolAddress((void**)&p_tmp,  g_tmp);
    cudaGetSymbolAddress((void**)&p_qkv,  g_qkv);
    cudaGetSymbolAddress((void**)&p_kvc,  g_kvc);
    cudaGetSymbolAddress((void**)&p_attn, g_attn);
    cudaGetSymbolAddress((void**)&p_sa,   g_sa);

    cudaFuncSetAttribute(flash_attn,
                         cudaFuncAttributeMaxDynamicSharedMemorySize, FA_SMEM);

    // 1. modulation vector
    modk<<<dim3(6 * D_ / 256, B_), 256>>>(t_emb, ada_w, ada_b);
    // 2. xm1 = ln(x)*(1+scale_sa)+shift_sa
    ln_mod<<<B_ * N_, 256>>>(x, p_tmp, p_mod, D_, 0);
    // 3. qkv
    mm_tc<0><<<dim3(3 * D_ / 128, B_ * N_ / 128), 256>>>(
        p_tmp, D_, qkv_w, 3 * D_, p_qkv, 3 * D_,
        qkv_b, nullptr, nullptr, B_ * N_, 3 * D_, D_);
    // 4. fused self-attention (QK^T -> softmax -> PV) -> g_sa
    flash_attn<<<dim3(N_ / 128, B_ * H_), 256, FA_SMEM>>>();
    // 5. x = x + gate_sa * (sa @ W + b)
    mm_tc<3><<<dim3(D_ / 128, B_ * N_ / 128), 256>>>(
        p_sa, D_, sa_w, D_, out, D_,
        sa_b, x, p_mod + 2 * D_, B_ * N_, D_, D_);
    // 6. xn2 = ln(x)
    ln_mod<<<B_ * N_, 256>>>(out, p_tmp, nullptr, 0, 0);
    // 7. qc (reuse g_qkv)
    mm_tc<0><<<dim3(D_ / 128, B_ * N_ / 128), 256>>>(
        p_tmp, D_, q_w, D_, p_qkv, D_,
        q_b, nullptr, nullptr, B_ * N_, D_, D_);
    // 8. kv from context (M=308, guarded)
    mm_tc<0><<<dim3(2 * D_ / 128, (B_ * S_ + 127) / 128), 256>>>(
        context, D_, kv_w, 2 * D_, p_kvc, 2 * D_,
        kv_b, nullptr, nullptr, B_ * S_, 2 * D_, D_);
    // 9. fused cross-attention -> g_sa
    cross_attn<<<dim3(N_, H_, B_), 128>>>(cmask);
    // 10. x = x + (ca @ W + b)
    mm_tc<2><<<dim3(D_ / 128, B_ * N_ / 128), 256>>>(
        p_sa, D_, ca_w, D_, out, D_,
        ca_b, out, nullptr, B_ * N_, D_, D_);
    // 11. xm3 = ln(x)*(1+scale_ff)+shift_ff
    ln_mod<<<B_ * N_, 256>>>(out, p_tmp, p_mod, 4 * D_, 3 * D_);
    // 12. h = gelu(xm3 @ fc1 + b)
    mm_tc<1><<<dim3(DF_ / 128, B_ * N_ / 128), 256>>>(
        p_tmp, D_, fc1_w, DF_, p_attn, DF_,
        fc1_b, nullptr, nullptr, B_ * N_, DF_, D_);
    // 13. x = x + gate_ff * (h @ fc2 + b)
    mm_tc<3><<<dim3(D_ / 128, B_ * N_ / 128), 256>>>(
        p_attn, DF_, fc2_w, D_, out, D_,
        fc2_b, out, p_mod + 5 * D_, B_ * N_, D_, DF_);
}

// round 8
// speedup vs baseline: 1.2195x; 1.1748x over previous
#include <cuda_runtime.h>
#include <math.h>

#define D_   1024
#define H_   16
#define B_   4
#define N_   1024
#define S_   77
#define HD_  64
#define DF_  4096
#define EPS_ 1e-6f
#define SCALE_ 0.125f   // HD^-0.5

// ---------------- scratch (device globals; no allocation allowed) ----------
__device__ float g_mod [B_ * 6 * D_];                  // modulation (B,6D)
__device__ float g_tmp [B_ * N_ * D_];                 // ln/modulated activations
__device__ float g_qkv [B_ * N_ * 3 * D_];             // qkv, later reused for qc
__device__ float g_kvc [B_ * S_ * 2 * D_];             // cross kv
__device__ float g_attn[(size_t)B_ * N_ * DF_];        // FF hidden
__device__ float g_sa  [B_ * N_ * D_];                 // attention outputs (pre-proj)

// ---------------- tf32 helpers ---------------------------------------------
__device__ __forceinline__ float f2tf32(float x) {
    unsigned r;
    asm("cvt.rna.tf32.f32 %0, %1;" : "=r"(r) : "f"(x));
    return __uint_as_float(r);
}

__device__ __forceinline__ void mma_tf32(float c[4], const unsigned a[4],
                                         unsigned b0, unsigned b1) {
    asm volatile(
        "mma.sync.aligned.m16n8k8.row.col.f32.tf32.tf32.f32 "
        "{%0,%1,%2,%3}, {%4,%5,%6,%7}, {%8,%9}, {%0,%1,%2,%3};\n"
        : "+f"(c[0]), "+f"(c[1]), "+f"(c[2]), "+f"(c[3])
        : "r"(a[0]), "r"(a[1]), "r"(a[2]), "r"(a[3]), "r"(b0), "r"(b1));
}

__device__ __forceinline__ void cp_async16(void* smem_dst, const void* gmem_src) {
    unsigned dst = (unsigned)__cvta_generic_to_shared(smem_dst);
    asm volatile("cp.async.cg.shared.global [%0], [%1], 16;\n"
                 :: "r"(dst), "l"(gmem_src));
}
// zero-fill variant: src_size=0 skips the read and fills zeros
__device__ __forceinline__ void cp_async16_z(void* smem_dst, const void* gmem_src, bool p) {
    unsigned dst = (unsigned)__cvta_generic_to_shared(smem_dst);
    int sz = p ? 16 : 0;
    asm volatile("cp.async.cg.shared.global [%0], [%1], 16, %2;\n"
                 :: "r"(dst), "l"(gmem_src), "r"(sz));
}
__device__ __forceinline__ void cp_commit() {
    asm volatile("cp.async.commit_group;\n" ::: "memory");
}
template<int N>
__device__ __forceinline__ void cp_wait() {
    asm volatile("cp.async.wait_group %0;\n" :: "n"(N) : "memory");
}

// ---------------- fused flash self-attention (tf32) -------------------------
// grid (N/128, B*H), 256 threads = 8 warps; each warp owns 16 Q rows.
#define FA_TILE  9216          // 128 * 72 floats
#define FA_SMEM  (5 * FA_TILE * 4)

__global__ __launch_bounds__(256) void flash_attn()
{
    extern __shared__ float sm[];
    float* Qs = sm;
    float* Ks[2] = { sm + FA_TILE,     sm + 2 * FA_TILE };
    float* Vs[2] = { sm + 3 * FA_TILE, sm + 4 * FA_TILE };

    const int tid = threadIdx.x;
    const int w    = tid >> 5;
    const int lane = tid & 31;
    const int g    = lane >> 2;
    const int tg   = lane & 3;

    const int bh = blockIdx.y;
    const int b  = bh >> 4, h = bh & 15;
    const int qrow0 = blockIdx.x * 128;

    const float* Qp = g_qkv + (long long)b * N_ * 3 * D_ + h * HD_;
    const float* Kp = Qp + D_;
    const float* Vp = Qp + 2 * D_;

    #pragma unroll
    for (int i = 0; i < 8; i++) {
        int c   = tid + i * 256;
        int row = c >> 4;
        int col = (c & 15) * 4;
        float4 v = *(const float4*)(Qp + (long long)(qrow0 + row) * 3072 + col);
        v.x = f2tf32(v.x * SCALE_); v.y = f2tf32(v.y * SCALE_);
        v.z = f2tf32(v.z * SCALE_); v.w = f2tf32(v.w * SCALE_);
        *(float4*)&Qs[row * 72 + col] = v;
    }

    auto loadTile = [&](const float* gbase, float* sbase) {
        #pragma unroll
        for (int i = 0; i < 8; i++) {
            int c   = tid + i * 256;
            int row = c >> 4;
            int col = (c & 15) * 4;
            cp_async16(sbase + row * 72 + col,
                       gbase + (long long)row * 3072 + col);
        }
    };
    loadTile(Kp, Ks[0]);
    loadTile(Vp, Vs[0]);
    cp_commit();

    __syncthreads();

    unsigned qa[8][4];
    {
        int r0 = w * 16 + g;
        #pragma unroll
        for (int ks = 0; ks < 8; ks++) {
            qa[ks][0] = __float_as_uint(Qs[r0 * 72 + ks * 8 + tg]);
            qa[ks][1] = __float_as_uint(Qs[(r0 + 8) * 72 + ks * 8 + tg]);
            qa[ks][2] = __float_as_uint(Qs[r0 * 72 + ks * 8 + tg + 4]);
            qa[ks][3] = __float_as_uint(Qs[(r0 + 8) * 72 + ks * 8 + tg + 4]);
        }
    }

    float o[8][4];
    #pragma unroll
    for (int i = 0; i < 8; i++)
        #pragma unroll
        for (int j = 0; j < 4; j++) o[i][j] = 0.f;
    float m0 = -1e30f, m1 = -1e30f, l0 = 0.f, l1 = 0.f;

    const unsigned fullm = 0xffffffffu;
    const int srcA = (lane & ~3) | (tg >> 1);
    const int srcB = srcA + 2;

    for (int t = 0; t < 8; t++) {
        if (t + 1 < 8) {
            loadTile(Kp + (long long)(t + 1) * 128 * 3072, Ks[(t + 1) & 1]);
            loadTile(Vp + (long long)(t + 1) * 128 * 3072, Vs[(t + 1) & 1]);
            cp_commit();
            cp_wait<1>();
        } else {
            cp_wait<0>();
        }
        __syncthreads();

        const float* K_ = Ks[t & 1];
        const float* V_ = Vs[t & 1];

        float s[16][4];
        #pragma unroll
        for (int nt = 0; nt < 16; nt++) {
            s[nt][0] = s[nt][1] = s[nt][2] = s[nt][3] = 0.f;
            #pragma unroll
            for (int ks = 0; ks < 8; ks++) {
                unsigned b0 = __float_as_uint(K_[(nt * 8 + g) * 72 + ks * 8 + tg]);
                unsigned b1 = __float_as_uint(K_[(nt * 8 + g) * 72 + ks * 8 + tg + 4]);
                mma_tf32(s[nt], qa[ks], b0, b1);
            }
        }

        float mx0 = -1e30f, mx1 = -1e30f;
        #pragma unroll
        for (int nt = 0; nt < 16; nt++) {
            mx0 = fmaxf(mx0, fmaxf(s[nt][0], s[nt][1]));
            mx1 = fmaxf(mx1, fmaxf(s[nt][2], s[nt][3]));
        }
        mx0 = fmaxf(mx0, __shfl_xor_sync(fullm, mx0, 1));
        mx0 = fmaxf(mx0, __shfl_xor_sync(fullm, mx0, 2));
        mx1 = fmaxf(mx1, __shfl_xor_sync(fullm, mx1, 1));
        mx1 = fmaxf(mx1, __shfl_xor_sync(fullm, mx1, 2));
        float mn0 = fmaxf(m0, mx0), mn1 = fmaxf(m1, mx1);
        float sc0 = __expf(m0 - mn0), sc1 = __expf(m1 - mn1);
        float rs0 = 0.f, rs1 = 0.f;
        #pragma unroll
        for (int nt = 0; nt < 16; nt++) {
            s[nt][0] = __expf(s[nt][0] - mn0);
            s[nt][1] = __expf(s[nt][1] - mn0);
            s[nt][2] = __expf(s[nt][2] - mn1);
            s[nt][3] = __expf(s[nt][3] - mn1);
            rs0 += s[nt][0] + s[nt][1];
            rs1 += s[nt][2] + s[nt][3];
        }
        rs0 += __shfl_xor_sync(fullm, rs0, 1);
        rs0 += __shfl_xor_sync(fullm, rs0, 2);
        rs1 += __shfl_xor_sync(fullm, rs1, 1);
        rs1 += __shfl_xor_sync(fullm, rs1, 2);
        l0 = l0 * sc0 + rs0;
        l1 = l1 * sc1 + rs1;
        m0 = mn0; m1 = mn1;
        #pragma unroll
        for (int nt = 0; nt < 8; nt++) {
            o[nt][0] *= sc0; o[nt][1] *= sc0;
            o[nt][2] *= sc1; o[nt][3] *= sc1;
        }

        #pragma unroll
        for (int kt = 0; kt < 16; kt++) {
            float p0 = s[kt][0], p1 = s[kt][1], p2 = s[kt][2], p3 = s[kt][3];
            float x0 = __shfl_sync(fullm, p0, srcA);
            float x1 = __shfl_sync(fullm, p1, srcA);
            float y0 = __shfl_sync(fullm, p2, srcA);
            float y1 = __shfl_sync(fullm, p3, srcA);
            float x0b = __shfl_sync(fullm, p0, srcB);
            float x1b = __shfl_sync(fullm, p1, srcB);
            float y0b = __shfl_sync(fullm, p2, srcB);
            float y1b = __shfl_sync(fullm, p3, srcB);
            unsigned a[4];
            a[0] = __float_as_uint((tg & 1) ? x1  : x0);
            a[1] = __float_as_uint((tg & 1) ? y1  : y0);
            a[2] = __float_as_uint((tg & 1) ? x1b : x0b);
            a[3] = __float_as_uint((tg & 1) ? y1b : y0b);
            #pragma unroll
            for (int nt = 0; nt < 8; nt++) {
                unsigned b0 = __float_as_uint(V_[(kt * 8 + tg) * 72 + nt * 8 + g]);
                unsigned b1 = __float_as_uint(V_[(kt * 8 + tg + 4) * 72 + nt * 8 + g]);
                mma_tf32(o[nt], a, b0, b1);
            }
        }
        __syncthreads();
    }

    float inv0 = 1.f / l0, inv1 = 1.f / l1;
    int row0 = qrow0 + w * 16 + g;
    float* op = g_sa + (long long)(b * N_ + row0) * D_ + h * HD_;
    #pragma unroll
    for (int nt = 0; nt < 8; nt++) {
        int col = nt * 8 + tg * 2;
        float2 lo = make_float2(o[nt][0] * inv0, o[nt][1] * inv0);
        float2 hi = make_float2(o[nt][2] * inv1, o[nt][3] * inv1);
        *(float2*)(op + col)            = lo;
        *(float2*)(op + 8 * D_ + col)   = hi;
    }
}

// ---------------- tensor-core tf32 GEMM, 3-stage cp.async pipeline ----------
// BM=128, BN=128, BK=32; 8 warps x 64x32; 2 CTAs/SM target.
// smem per stage: As 128x36 + Bs 32x136 floats = 8960 floats (35840 B); x3 stages.
// MODE: 0 = bias, 1 = bias+gelu, 2 = bias+residual, 3 = bias+gate*val+residual
#define MM_STG   8960
#define MM_SMEM  (3 * MM_STG * 4)

template<int MODE>
__global__ __launch_bounds__(256, 2) void mm_tc(
    const float* __restrict__ A,  int lda,
    const float* __restrict__ Bm, int ldb,
    float* __restrict__ C,        int ldc,
    const float* __restrict__ bias,
    const float* __restrict__ res,
    const float* __restrict__ gate,
    int M, int Ncols, int K)
{
    extern __shared__ float smm[];

    const int tid     = threadIdx.x;
    const int rowBase = blockIdx.y * 128;
    const int colBase = blockIdx.x * 128;

    const int warp  = tid >> 5;
    const int lane  = tid & 31;
    const int warpM = (warp >> 2) * 64;
    const int warpN = (warp & 3) * 32;
    const int g     = lane >> 2;
    const int tg    = lane & 3;

    float acc[4][4][4];
    #pragma unroll
    for (int i = 0; i < 4; i++)
        #pragma unroll
        for (int j = 0; j < 4; j++)
            #pragma unroll
            for (int t = 0; t < 4; t++) acc[i][j][t] = 0.f;

    // per-thread load coords (4 x 16B for A, 4 x 16B for B)
    const int amr = tid >> 3;            // A row within tile batch of 32-row steps
    const int ak4 = (tid & 7) * 4;       // A k offset
    const int bkk = tid >> 5;            // B k row step base
    const int bn4 = (tid & 31) * 4;      // B col offset

    auto issueTile = [&](int kt, int s) {
        float* as = smm + s * MM_STG;
        float* bs = as + 4608;           // 128*36
        int k0 = kt * 32;
        #pragma unroll
        for (int i = 0; i < 4; i++) {
            int m  = amr + i * 32;
            int gr = rowBase + m;
            cp_async16_z(&as[m * 36 + ak4],
                         A + (long long)gr * lda + k0 + ak4, gr < M);
        }
        #pragma unroll
        for (int i = 0; i < 4; i++) {
            int kk = bkk + i * 8;
            cp_async16(&bs[kk * 136 + bn4],
                       Bm + (long long)(k0 + kk) * ldb + colBase + bn4);
        }
    };

    const int KT = K >> 5;
    issueTile(0, 0); cp_commit();
    issueTile(1, 1); cp_commit();

    int s = 0;
    for (int kt = 0; kt < KT; kt++) {
        if (kt + 2 < KT) issueTile(kt + 2, (s + 2) % 3);
        cp_commit();
        cp_wait<2>();
        __syncthreads();

        const float* As_ = smm + s * MM_STG;
        const float* Bs_ = As_ + 4608;

        #pragma unroll
        for (int ks = 0; ks < 4; ks++) {
            int k = ks * 8 + tg;
            unsigned a[4][4];
            #pragma unroll
            for (int mt = 0; mt < 4; mt++) {
                int m = warpM + mt * 16 + g;
                a[mt][0] = __float_as_uint(As_[m * 36 + k]);
                a[mt][1] = __float_as_uint(As_[(m + 8) * 36 + k]);
                a[mt][2] = __float_as_uint(As_[m * 36 + k + 4]);
                a[mt][3] = __float_as_uint(As_[(m + 8) * 36 + k + 4]);
            }
            #pragma unroll
            for (int nt = 0; nt < 4; nt++) {
                int n = warpN + nt * 8 + g;
                unsigned b0 = __float_as_uint(Bs_[k * 136 + n]);
                unsigned b1 = __float_as_uint(Bs_[(k + 4) * 136 + n]);
                #pragma unroll
                for (int mt = 0; mt < 4; mt++)
                    mma_tf32(acc[mt][nt], a[mt], b0, b1);
            }
        }
        __syncthreads();
        s = (s + 1) % 3;
    }

    #pragma unroll
    for (int mt = 0; mt < 4; mt++) {
        #pragma unroll
        for (int half = 0; half < 2; half++) {
            int row = rowBase + warpM + mt * 16 + g + half * 8;
            if (row >= M) continue;
            #pragma unroll
            for (int nt = 0; nt < 4; nt++) {
                int col = colBase + warpN + nt * 8 + tg * 2;
                #pragma unroll
                for (int e = 0; e < 2; e++) {
                    float v = acc[mt][nt][half * 2 + e];
                    int cc = col + e;
                    if (bias) v += bias[cc];
                    long long idx = (long long)row * ldc + cc;
                    if (MODE == 1) {
                        v = 0.5f * v * (1.0f + erff(v * 0.70710678118654752f));
                    } else if (MODE == 2) {
                        v = res[idx] + v;
                    } else if (MODE == 3) {
                        int bb = row >> 10;
                        v = res[idx] + gate[(long long)bb * (6 * D_) + cc] * v;
                    }
                    C[idx] = v;
                }
            }
        }
    }
}

// ---------------- mod = silu(t_emb) @ ada_w + ada_b ------------------------
__global__ __launch_bounds__(256) void modk(const float* __restrict__ t_emb,
                                            const float* __restrict__ ada_w,
                                            const float* __restrict__ ada_b)
{
    __shared__ float sact[D_];
    int b   = blockIdx.y;
    int col = blockIdx.x * 256 + threadIdx.x;
    for (int i = threadIdx.x; i < D_; i += 256) {
        float t = t_emb[b * D_ + i];
        sact[i] = t / (1.f + expf(-t));
    }
    __syncthreads();
    float acc = ada_b[col];
    for (int k = 0; k < D_; k++)
        acc += sact[k] * ada_w[(long long)k * (6 * D_) + col];
    g_mod[(long long)b * 6 * D_ + col] = acc;
}

// ---------------- layernorm (+ optional adaLN modulation) ------------------
__global__ __launch_bounds__(256) void ln_mod(const float* __restrict__ x,
                                              float* __restrict__ out,
                                              const float* __restrict__ mod,
                                              int scaleOff, int shiftOff)
{
    long long row = blockIdx.x;
    int b = (int)(row >> 10);
    const float4* p = (const float4*)(x + row * D_);
    float4* q = (float4*)(out + row * D_);
    int tid = threadIdx.x;
    float4 v = p[tid];
    float s  = v.x + v.y + v.z + v.w;
    float s2 = v.x*v.x + v.y*v.y + v.z*v.z + v.w*v.w;
    __shared__ float r1[8], r2[8];
    __shared__ float s_mean, s_rstd;
    #pragma unroll
    for (int o = 16; o > 0; o >>= 1) {
        s  += __shfl_xor_sync(0xffffffffu, s,  o);
        s2 += __shfl_xor_sync(0xffffffffu, s2, o);
    }
    if ((tid & 31) == 0) { r1[tid >> 5] = s; r2[tid >> 5] = s2; }
    __syncthreads();
    if (tid == 0) {
        float a = 0.f, bb = 0.f;
        for (int i = 0; i < 8; i++) { a += r1[i]; bb += r2[i]; }
        float mean = a * (1.f / D_);
        float var  = bb * (1.f / D_) - mean * mean;
        s_mean = mean;
        s_rstd = rsqrtf(var + EPS_);
    }
    __syncthreads();
    float mean = s_mean, rstd = s_rstd;
    float4 o;
    o.x = (v.x - mean) * rstd;
    o.y = (v.y - mean) * rstd;
    o.z = (v.z - mean) * rstd;
    o.w = (v.w - mean) * rstd;
    if (mod) {
        const float* mrow = mod + (long long)b * 6 * D_;
        int col = tid * 4;
        o.x = o.x * (1.f + mrow[scaleOff + col + 0]) + mrow[shiftOff + col + 0];
        o.y = o.y * (1.f + mrow[scaleOff + col + 1]) + mrow[shiftOff + col + 1];
        o.z = o.z * (1.f + mrow[scaleOff + col + 2]) + mrow[shiftOff + col + 2];
        o.w = o.w * (1.f + mrow[scaleOff + col + 3]) + mrow[shiftOff + col + 3];
    }
    q[tid] = o;
}

// ---------------- fused cross-attention (S=77) -----------------------------
__global__ __launch_bounds__(128) void cross_attn(const unsigned char* __restrict__ mask)
{
    int n = blockIdx.x, h = blockIdx.y, b = blockIdx.z;
    __shared__ float qv[HD_];
    __shared__ float sc[S_];
    __shared__ float s_m, s_sum;
    int tid = threadIdx.x;
    if (tid < HD_)
        qv[tid] = g_qkv[(long long)(b * N_ + n) * D_ + h * HD_ + tid];
    __syncthreads();
    if (tid < S_) {
        const float* kp = g_kvc + ((long long)(b * S_ + tid) * 2) * D_ + h * HD_;
        float s = 0.f;
        #pragma unroll
        for (int d = 0; d < HD_; d++) s += qv[d] * kp[d];
        s *= SCALE_;
        if (mask[b * S_ + tid]) s = -1e30f;
        sc[tid] = s;
    }
    __syncthreads();
    if (tid == 0) {
        float m = -1e30f;
        for (int i = 0; i < S_; i++) m = fmaxf(m, sc[i]);
        s_m = m;
    }
    __syncthreads();
    if (tid < S_) sc[tid] = expf(sc[tid] - s_m);
    __syncthreads();
    if (tid == 0) {
        float s = 0.f;
        for (int i = 0; i < S_; i++) s += sc[i];
        s_sum = s;
    }
    __syncthreads();
    if (tid < HD_) {
        float o = 0.f;
        for (int si = 0; si < S_; si++)
            o += sc[si] * g_kvc[((long long)(b * S_ + si) * 2 + 1) * D_ + h * HD_ + tid];
        g_sa[(long long)(b * N_ + n) * D_ + h * HD_ + tid] = o / s_sum;
    }
}

// ---------------- host orchestration ---------------------------------------
extern "C" void kernel_launch(void* const* d_in, const int* in_sizes, int n_in,
                              void* d_out, int out_size)
{
    const float* x       = (const float*)d_in[0];
    const float* t_emb   = (const float*)d_in[1];
    const float* context = (const float*)d_in[2];
    const unsigned char* cmask = (const unsigned char*)d_in[3];
    const float* ada_w = (const float*)d_in[4];  const float* ada_b = (const float*)d_in[5];
    const float* qkv_w = (const float*)d_in[6];  const float* qkv_b = (const float*)d_in[7];
    const float* sa_w  = (const float*)d_in[8];  const float* sa_b  = (const float*)d_in[9];
    const float* q_w   = (const float*)d_in[10]; const float* q_b   = (const float*)d_in[11];
    const float* kv_w  = (const float*)d_in[12]; const float* kv_b  = (const float*)d_in[13];
    const float* ca_w  = (const float*)d_in[14]; const float* ca_b  = (const float*)d_in[15];
    const float* fc1_w = (const float*)d_in[16]; const float* fc1_b = (const float*)d_in[17];
    const float* fc2_w = (const float*)d_in[18]; const float* fc2_b = (const float*)d_in[19];
    float* out = (float*)d_out;

    float *p_mod, *p_tmp, *p_qkv, *p_kvc, *p_attn, *p_sa;
    cudaGetSymbolAddress((void**)&p_mod,  g_mod);
    cudaGetSymbolAddress((void**)&p_tmp,  g_tmp);
    cudaGetSymbolAddress((void**)&p_qkv,  g_qkv);
    cudaGetSymbolAddress((void**)&p_kvc,  g_kvc);
    cudaGetSymbolAddress((void**)&p_attn, g_attn);
    cudaGetSymbolAddress((void**)&p_sa,   g_sa);

    cudaFuncSetAttribute(flash_attn,
                         cudaFuncAttributeMaxDynamicSharedMemorySize, FA_SMEM);
    cudaFuncSetAttribute(mm_tc<0>, cudaFuncAttributeMaxDynamicSharedMemorySize, MM_SMEM);
    cudaFuncSetAttribute(mm_tc<1>, cudaFuncAttributeMaxDynamicSharedMemorySize, MM_SMEM);
    cudaFuncSetAttribute(mm_tc<2>, cudaFuncAttributeMaxDynamicSharedMemorySize, MM_SMEM);
    cudaFuncSetAttribute(mm_tc<3>, cudaFuncAttributeMaxDynamicSharedMemorySize, MM_SMEM);

    // 1. modulation vector
    modk<<<dim3(6 * D_ / 256, B_), 256>>>(t_emb, ada_w, ada_b);
    // 2. xm1 = ln(x)*(1+scale_sa)+shift_sa
    ln_mod<<<B_ * N_, 256>>>(x, p_tmp, p_mod, D_, 0);
    // 3. qkv
    mm_tc<0><<<dim3(3 * D_ / 128, B_ * N_ / 128), 256, MM_SMEM>>>(
        p_tmp, D_, qkv_w, 3 * D_, p_qkv, 3 * D_,
        qkv_b, nullptr, nullptr, B_ * N_, 3 * D_, D_);
    // 4. fused self-attention -> g_sa
    flash_attn<<<dim3(N_ / 128, B_ * H_), 256, FA_SMEM>>>();
    // 5. x = x + gate_sa * (sa @ W + b)
    mm_tc<3><<<dim3(D_ / 128, B_ * N_ / 128), 256, MM_SMEM>>>(
        p_sa, D_, sa_w, D_, out, D_,
        sa_b, x, p_mod + 2 * D_, B_ * N_, D_, D_);
    // 6. xn2 = ln(x)
    ln_mod<<<B_ * N_, 256>>>(out, p_tmp, nullptr, 0, 0);
    // 7. qc (reuse g_qkv)
    mm_tc<0><<<dim3(D_ / 128, B_ * N_ / 128), 256, MM_SMEM>>>(
        p_tmp, D_, q_w, D_, p_qkv, D_,
        q_b, nullptr, nullptr, B_ * N_, D_, D_);
    // 8. kv from context (M=308, zero-fill guarded)
    mm_tc<0><<<dim3(2 * D_ / 128, (B_ * S_ + 127) / 128), 256, MM_SMEM>>>(
        context, D_, kv_w, 2 * D_, p_kvc, 2 * D_,
        kv_b, nullptr, nullptr, B_ * S_, 2 * D_, D_);
    // 9. fused cross-attention -> g_sa
    cross_attn<<<dim3(N_, H_, B_), 128>>>(cmask);
    // 10. x = x + (ca @ W + b)
    mm_tc<2><<<dim3(D_ / 128, B_ * N_ / 128), 256, MM_SMEM>>>(
        p_sa, D_, ca_w, D_, out, D_,
        ca_b, out, nullptr, B_ * N_, D_, D_);
    // 11. xm3 = ln(x)*(1+scale_ff)+shift_ff
    ln_mod<<<B_ * N_, 256>>>(out, p_tmp, p_mod, 4 * D_, 3 * D_);
    // 12. h = gelu(xm3 @ fc1 + b)
    mm_tc<1><<<dim3(DF_ / 128, B_ * N_ / 128), 256, MM_SMEM>>>(
        p_tmp, D_, fc1_w, DF_, p_attn, DF_,
        fc1_b, nullptr, nullptr, B_ * N_, DF_, D_);
    // 13. x = x + gate_ff * (h @ fc2 + b)
    mm_tc<3><<<dim3(D_ / 128, B_ * N_ / 128), 256, MM_SMEM>>>(
        p_attn, DF_, fc2_w, D_, out, D_,
        fc2_b, out, p_mod + 5 * D_, B_ * N_, D_, DF_);
}